// round 1
// baseline (speedup 1.0000x reference)
#include <cuda_runtime.h>
#include <math_constants.h>

#define HIDDEN   1024
#define HEADS    16
#define HEAD_DIM 64
#define BATCH    2
#define SEQ      2048
#define NTOK     (BATCH * SEQ)   // 4096
#define LN_EPS   1e-6f
#define ATT_SCALE 0.125f         // 1/sqrt(64)

// ---------------- scratch (no allocations allowed) ----------------
__device__ float g_q[NTOK * HIDDEN];    // [B, h, S, d]
__device__ float g_k[NTOK * HIDDEN];    // [B, h, S, d]
__device__ float g_v[NTOK * HIDDEN];    // [B, h, S, d]
__device__ float g_ctx[NTOK * HIDDEN];  // [tok, H]
__device__ float g_res[NTOK * HIDDEN];  // [tok, H]

// =================================================================
// Kernel 1: fused QKV projection.  y = x @ W^T + b
// x: [4096, 1024] row-major, W: [1024, 1024] row-major (NT gemm).
// Output written directly in attention layout [B, h, S, d].
// grid (8 jtiles, 32 mtiles, 3 matrices), block 256.
// =================================================================
__global__ __launch_bounds__(256) void qkv_gemm_kernel(
    const float* __restrict__ x,
    const float* __restrict__ Wq, const float* __restrict__ bq,
    const float* __restrict__ Wk, const float* __restrict__ bk,
    const float* __restrict__ Wv, const float* __restrict__ bv)
{
    const float* W;
    const float* bias;
    float* out;
    int z = blockIdx.z;
    if (z == 0)      { W = Wq; bias = bq; out = g_q; }
    else if (z == 1) { W = Wk; bias = bk; out = g_k; }
    else             { W = Wv; bias = bv; out = g_v; }

    __shared__ float As[8][132];
    __shared__ float Bs[8][132];

    const int tid = threadIdx.x;
    const int m0 = blockIdx.y * 128;
    const int j0 = blockIdx.x * 128;
    const int ldrow = tid >> 1;          // 0..127
    const int ldkc  = (tid & 1) * 4;     // 0 or 4
    const int tx = tid & 15;
    const int ty = tid >> 4;

    float acc[8][8];
    #pragma unroll
    for (int i = 0; i < 8; i++)
        #pragma unroll
        for (int j = 0; j < 8; j++) acc[i][j] = 0.f;

    const float4* Ag = (const float4*)(x + (size_t)(m0 + ldrow) * HIDDEN);
    const float4* Bg = (const float4*)(W + (size_t)(j0 + ldrow) * HIDDEN);

    for (int kk = 0; kk < HIDDEN; kk += 8) {
        float4 a = Ag[(kk + ldkc) >> 2];
        float4 b = Bg[(kk + ldkc) >> 2];
        As[ldkc + 0][ldrow] = a.x; As[ldkc + 1][ldrow] = a.y;
        As[ldkc + 2][ldrow] = a.z; As[ldkc + 3][ldrow] = a.w;
        Bs[ldkc + 0][ldrow] = b.x; Bs[ldkc + 1][ldrow] = b.y;
        Bs[ldkc + 2][ldrow] = b.z; Bs[ldkc + 3][ldrow] = b.w;
        __syncthreads();

        #pragma unroll
        for (int k = 0; k < 8; k++) {
            float av[8], bv8[8];
            float4 t;
            t = *(const float4*)&As[k][ty * 8];     av[0]=t.x; av[1]=t.y; av[2]=t.z; av[3]=t.w;
            t = *(const float4*)&As[k][ty * 8 + 4]; av[4]=t.x; av[5]=t.y; av[6]=t.z; av[7]=t.w;
            t = *(const float4*)&Bs[k][tx * 8];     bv8[0]=t.x; bv8[1]=t.y; bv8[2]=t.z; bv8[3]=t.w;
            t = *(const float4*)&Bs[k][tx * 8 + 4]; bv8[4]=t.x; bv8[5]=t.y; bv8[6]=t.z; bv8[7]=t.w;
            #pragma unroll
            for (int ii = 0; ii < 8; ii++)
                #pragma unroll
                for (int jj = 0; jj < 8; jj++)
                    acc[ii][jj] += av[ii] * bv8[jj];
        }
        __syncthreads();
    }

    #pragma unroll
    for (int jj = 0; jj < 8; jj++) {
        int j = j0 + tx * 8 + jj;
        float bj = bias[j];
        int h = j >> 6, dd = j & 63;
        #pragma unroll
        for (int ii = 0; ii < 8; ii++) {
            int m = m0 + ty * 8 + ii;
            int bb = m >> 11, s = m & (SEQ - 1);
            out[(((size_t)bb * HEADS + h) * SEQ + s) * HEAD_DIM + dd] = acc[ii][jj] + bj;
        }
    }
}

// =================================================================
// Kernel 2: flash attention, fp32 SIMT.
// grid (S/32 = 64 qtiles, B*HEADS = 32), block 128 (4 warps).
// Each warp owns 8 query rows; each lane owns one key per 32-key tile
// and two output columns.
// =================================================================
__global__ __launch_bounds__(128) void attn_kernel(const int* __restrict__ mask)
{
    const int bh = blockIdx.y;
    const int b = bh / HEADS;
    const int h = bh % HEADS;
    const int q0 = blockIdx.x * 32;
    const int tid = threadIdx.x;
    const int lane = tid & 31;
    const int warp = tid >> 5;
    const int r0 = warp * 8;

    __shared__ float  Qs[32][68];
    __shared__ float2 Vs[32][32];

    // load Q tile [32 x 64] (contiguous chunk of g_q)
    const float4* Qg = (const float4*)(g_q + ((size_t)bh * SEQ + q0) * HEAD_DIM);
    #pragma unroll
    for (int i = 0; i < 4; i++) {
        int idx4 = tid + i * 128;        // 0..511 float4s
        int row = idx4 >> 4;
        int c4  = idx4 & 15;
        float4 v = Qg[idx4];
        *(float4*)&Qs[row][c4 * 4] = v;
    }

    float mrow[8], lrow[8], o0[8], o1[8];
    #pragma unroll
    for (int r = 0; r < 8; r++) {
        mrow[r] = -CUDART_INF_F; lrow[r] = 0.f; o0[r] = 0.f; o1[r] = 0.f;
    }

    const float4* Kg = (const float4*)(g_k + (size_t)bh * SEQ * HEAD_DIM);
    const float2* Vg = (const float2*)(g_v + (size_t)bh * SEQ * HEAD_DIM);
    const int* maskb = mask + b * SEQ;

    for (int k0 = 0; k0 < SEQ; k0 += 32) {
        __syncthreads();   // protect Vs from previous tile's readers
        // V tile: contiguous 1024 float2s
        #pragma unroll
        for (int i = 0; i < 8; i++) {
            int idx = tid + i * 128;
            ((float2*)Vs)[idx] = Vg[(size_t)k0 * 32 + idx];
        }
        __syncthreads();

        // K column for this lane -> registers (64 floats)
        float4 kr[16];
        #pragma unroll
        for (int i = 0; i < 16; i++) kr[i] = Kg[(size_t)(k0 + lane) * 16 + i];

        float biasv = (1.0f - (float)maskb[k0 + lane]) * -1e18f;

        #pragma unroll
        for (int r = 0; r < 8; r++) {
            const float4* qrow = (const float4*)&Qs[r0 + r][0];
            float s = 0.f;
            #pragma unroll
            for (int i = 0; i < 16; i++) {
                float4 q = qrow[i];
                s += q.x * kr[i].x + q.y * kr[i].y + q.z * kr[i].z + q.w * kr[i].w;
            }
            s = s * ATT_SCALE + biasv;

            float tm = s;
            #pragma unroll
            for (int off = 16; off > 0; off >>= 1)
                tm = fmaxf(tm, __shfl_xor_sync(0xffffffffu, tm, off));
            float mnew = fmaxf(mrow[r], tm);
            float p = __expf(s - mnew);
            float alpha = __expf(mrow[r] - mnew);
            float ps = p;
            #pragma unroll
            for (int off = 16; off > 0; off >>= 1)
                ps += __shfl_xor_sync(0xffffffffu, ps, off);
            lrow[r] = lrow[r] * alpha + ps;
            mrow[r] = mnew;
            o0[r] *= alpha; o1[r] *= alpha;

            #pragma unroll
            for (int k = 0; k < 32; k++) {
                float pk = __shfl_sync(0xffffffffu, p, k);
                float2 v = Vs[k][lane];
                o0[r] += pk * v.x;
                o1[r] += pk * v.y;
            }
        }
    }

    // write ctx token-major [tok, H]
    #pragma unroll
    for (int r = 0; r < 8; r++) {
        int tok = b * SEQ + q0 + r0 + r;
        float inv = 1.0f / lrow[r];
        float* dst = g_ctx + (size_t)tok * HIDDEN + h * HEAD_DIM + lane * 2;
        dst[0] = o0[r] * inv;
        dst[1] = o1[r] * inv;
    }
}

// =================================================================
// Kernel 3: output projection + bias + residual.
// res = ctx @ Wo^T + bo + x ; grid (8, 32), block 256.
// =================================================================
__global__ __launch_bounds__(256) void oproj_gemm_kernel(
    const float* __restrict__ x,
    const float* __restrict__ Wo, const float* __restrict__ bo)
{
    __shared__ float As[8][132];
    __shared__ float Bs[8][132];

    const int tid = threadIdx.x;
    const int m0 = blockIdx.y * 128;
    const int j0 = blockIdx.x * 128;
    const int ldrow = tid >> 1;
    const int ldkc  = (tid & 1) * 4;
    const int tx = tid & 15;
    const int ty = tid >> 4;

    float acc[8][8];
    #pragma unroll
    for (int i = 0; i < 8; i++)
        #pragma unroll
        for (int j = 0; j < 8; j++) acc[i][j] = 0.f;

    const float4* Ag = (const float4*)(g_ctx + (size_t)(m0 + ldrow) * HIDDEN);
    const float4* Bg = (const float4*)(Wo + (size_t)(j0 + ldrow) * HIDDEN);

    for (int kk = 0; kk < HIDDEN; kk += 8) {
        float4 a = Ag[(kk + ldkc) >> 2];
        float4 b = Bg[(kk + ldkc) >> 2];
        As[ldkc + 0][ldrow] = a.x; As[ldkc + 1][ldrow] = a.y;
        As[ldkc + 2][ldrow] = a.z; As[ldkc + 3][ldrow] = a.w;
        Bs[ldkc + 0][ldrow] = b.x; Bs[ldkc + 1][ldrow] = b.y;
        Bs[ldkc + 2][ldrow] = b.z; Bs[ldkc + 3][ldrow] = b.w;
        __syncthreads();

        #pragma unroll
        for (int k = 0; k < 8; k++) {
            float av[8], bv8[8];
            float4 t;
            t = *(const float4*)&As[k][ty * 8];     av[0]=t.x; av[1]=t.y; av[2]=t.z; av[3]=t.w;
            t = *(const float4*)&As[k][ty * 8 + 4]; av[4]=t.x; av[5]=t.y; av[6]=t.z; av[7]=t.w;
            t = *(const float4*)&Bs[k][tx * 8];     bv8[0]=t.x; bv8[1]=t.y; bv8[2]=t.z; bv8[3]=t.w;
            t = *(const float4*)&Bs[k][tx * 8 + 4]; bv8[4]=t.x; bv8[5]=t.y; bv8[6]=t.z; bv8[7]=t.w;
            #pragma unroll
            for (int ii = 0; ii < 8; ii++)
                #pragma unroll
                for (int jj = 0; jj < 8; jj++)
                    acc[ii][jj] += av[ii] * bv8[jj];
        }
        __syncthreads();
    }

    #pragma unroll
    for (int jj = 0; jj < 8; jj++) {
        int j = j0 + tx * 8 + jj;
        float bj = bo[j];
        #pragma unroll
        for (int ii = 0; ii < 8; ii++) {
            int m = m0 + ty * 8 + ii;
            size_t idx = (size_t)m * HIDDEN + j;
            g_res[idx] = acc[ii][jj] + bj + x[idx];
        }
    }
}

// =================================================================
// Kernel 4: LayerNorm over last dim (1024). One block per token row.
// =================================================================
__global__ __launch_bounds__(256) void ln_kernel(
    const float* __restrict__ gamma, const float* __restrict__ beta,
    float* __restrict__ out)
{
    const int rowi = blockIdx.x;
    const int tid = threadIdx.x;
    const int lane = tid & 31;
    const int warp = tid >> 5;

    __shared__ float red[8];
    __shared__ float mean_s, rstd_s;

    const float4* src = (const float4*)(g_res + (size_t)rowi * HIDDEN);
    float4 v = src[tid];

    float sum = v.x + v.y + v.z + v.w;
    #pragma unroll
    for (int off = 16; off > 0; off >>= 1) sum += __shfl_xor_sync(0xffffffffu, sum, off);
    if (lane == 0) red[warp] = sum;
    __syncthreads();
    if (tid == 0) {
        float t = 0.f;
        #pragma unroll
        for (int i = 0; i < 8; i++) t += red[i];
        mean_s = t * (1.0f / HIDDEN);
    }
    __syncthreads();
    float mean = mean_s;

    float dx = v.x - mean, dy = v.y - mean, dz = v.z - mean, dw = v.w - mean;
    float sq = dx * dx + dy * dy + dz * dz + dw * dw;
    #pragma unroll
    for (int off = 16; off > 0; off >>= 1) sq += __shfl_xor_sync(0xffffffffu, sq, off);
    if (lane == 0) red[warp] = sq;
    __syncthreads();
    if (tid == 0) {
        float t = 0.f;
        #pragma unroll
        for (int i = 0; i < 8; i++) t += red[i];
        rstd_s = rsqrtf(t * (1.0f / HIDDEN) + LN_EPS);
    }
    __syncthreads();
    float rstd = rstd_s;

    float4 g = ((const float4*)gamma)[tid];
    float4 bb = ((const float4*)beta)[tid];
    float4 o;
    o.x = dx * rstd * g.x + bb.x;
    o.y = dy * rstd * g.y + bb.y;
    o.z = dz * rstd * g.z + bb.z;
    o.w = dw * rstd * g.w + bb.w;
    ((float4*)(out + (size_t)rowi * HIDDEN))[tid] = o;
}

// =================================================================
extern "C" void kernel_launch(void* const* d_in, const int* in_sizes, int n_in,
                              void* d_out, int out_size)
{
    const float* x    = (const float*)d_in[0];
    const int*   mask = (const int*)  d_in[1];
    const float* Wq   = (const float*)d_in[2];
    const float* bq   = (const float*)d_in[3];
    const float* Wk   = (const float*)d_in[4];
    const float* bk   = (const float*)d_in[5];
    const float* Wv   = (const float*)d_in[6];
    const float* bv   = (const float*)d_in[7];
    const float* Wo   = (const float*)d_in[8];
    const float* bo   = (const float*)d_in[9];
    const float* lng  = (const float*)d_in[10];
    const float* lnb  = (const float*)d_in[11];
    float* out = (float*)d_out;

    qkv_gemm_kernel<<<dim3(8, 32, 3), 256>>>(x, Wq, bq, Wk, bk, Wv, bv);
    attn_kernel<<<dim3(SEQ / 32, BATCH * HEADS), 128>>>(mask);
    oproj_gemm_kernel<<<dim3(8, 32), 256>>>(x, Wo, bo);
    ln_kernel<<<NTOK, 256>>>(lng, lnb, out);
}

// round 4
// speedup vs baseline: 1.2137x; 1.2137x over previous
#include <cuda_runtime.h>
#include <cuda_fp16.h>
#include <math_constants.h>

#define HIDDEN   1024
#define HEADS    16
#define HEAD_DIM 64
#define BATCH    2
#define SEQ      2048
#define NTOK     (BATCH * SEQ)   // 4096
#define LN_EPS   1e-6f
#define ATT_SCALE 0.125f         // 1/sqrt(64)

typedef unsigned int       u32;
typedef unsigned long long u64;

// ---------------- scratch (no allocations allowed) ----------------
__device__ float g_q[NTOK * HIDDEN];    // [B, h, S, d]
__device__ float g_k[NTOK * HIDDEN];    // [B, h, S, d]
__device__ float g_v[NTOK * HIDDEN];    // [B, h, S, d]
__device__ float g_ctx[NTOK * HIDDEN];  // [tok, H]
__device__ float g_res[NTOK * HIDDEN];  // [tok, H]
// fp16 hi/lo splits
__device__ __half g_xh[NTOK * HIDDEN],        g_xl[NTOK * HIDDEN];
__device__ __half g_wh[3 * HIDDEN * HIDDEN],  g_wl[3 * HIDDEN * HIDDEN];   // Wq|Wk|Wv
__device__ __half g_woh[HIDDEN * HIDDEN],     g_wol[HIDDEN * HIDDEN];
__device__ __half g_ch[NTOK * HIDDEN],        g_cl[NTOK * HIDDEN];

// =================================================================
// helpers
// =================================================================
__device__ __forceinline__ u32 smem_u32(const void* p) {
    u32 a;
    asm("{ .reg .u64 t; cvta.to.shared.u64 t, %1; cvt.u32.u64 %0, t; }" : "=r"(a) : "l"(p));
    return a;
}
// swizzle for 64-byte rows: XOR byte bits[5:4] with row bits (offset bits [8:7])
#define SWZ64(o) ((o) ^ (((o) >> 3) & 0x30))

#define CP_ASYNC16(dst_u32, src_ptr) \
    asm volatile("cp.async.cg.shared.global [%0], [%1], 16;" :: "r"(dst_u32), "l"(src_ptr) : "memory")
#define CP_COMMIT() asm volatile("cp.async.commit_group;" ::: "memory")
#define CP_WAIT(n)  asm volatile("cp.async.wait_group %0;" :: "n"(n) : "memory")

#define LDSM_X4(r0, r1, r2, r3, addr) \
    asm volatile("ldmatrix.sync.aligned.m8n8.x4.shared.b16 {%0,%1,%2,%3}, [%4];" \
                 : "=r"(r0), "=r"(r1), "=r"(r2), "=r"(r3) : "r"(addr))
#define LDSM_X2(r0, r1, addr) \
    asm volatile("ldmatrix.sync.aligned.m8n8.x2.shared.b16 {%0,%1}, [%2];" \
                 : "=r"(r0), "=r"(r1) : "r"(addr))

#define MMA16816(d, a, b) \
    asm volatile("mma.sync.aligned.m16n8k16.row.col.f32.f16.f16.f32 " \
                 "{%0,%1,%2,%3}, {%4,%5,%6,%7}, {%8,%9}, {%0,%1,%2,%3};" \
                 : "+f"((d)[0]), "+f"((d)[1]), "+f"((d)[2]), "+f"((d)[3]) \
                 : "r"((a)[0]), "r"((a)[1]), "r"((a)[2]), "r"((a)[3]), \
                   "r"((b)[0]), "r"((b)[1]))

// =================================================================
// split: fp32 -> (fp16 hi, fp16 lo)
// =================================================================
__global__ __launch_bounds__(256) void split_kernel(
    const float* __restrict__ src, __half* __restrict__ hi, __half* __restrict__ lo, int n4)
{
    int i = blockIdx.x * blockDim.x + threadIdx.x;
    if (i >= n4) return;
    float4 v = ((const float4*)src)[i];
    __half h0 = __float2half_rn(v.x), h1 = __float2half_rn(v.y);
    __half h2 = __float2half_rn(v.z), h3 = __float2half_rn(v.w);
    __half l0 = __float2half_rn(v.x - __half2float(h0));
    __half l1 = __float2half_rn(v.y - __half2float(h1));
    __half l2 = __float2half_rn(v.z - __half2float(h2));
    __half l3 = __float2half_rn(v.w - __half2float(h3));
    ((__half2*)hi)[2 * i]     = __halves2half2(h0, h1);
    ((__half2*)hi)[2 * i + 1] = __halves2half2(h2, h3);
    ((__half2*)lo)[2 * i]     = __halves2half2(l0, l1);
    ((__half2*)lo)[2 * i + 1] = __halves2half2(l2, l3);
}

// =================================================================
// HMMA GEMM: C[m,n] = sum_k A[m,k]*B[n,k], fp16 hi/lo (3 passes),
// fp32 accum. CTA tile 128x128, BK=32, 8 warps (2m x 4n), warp tile
// 64x32, double-buffered cp.async.
// mode 0: QKV epilogue (+bias, scatter to g_q/g_k/g_v [B,h,S,d])
// mode 1: O-proj epilogue (+bias +residual -> g_res)
// =================================================================
__global__ __launch_bounds__(256) void gemm_hmma_kernel(
    const __half* __restrict__ Ah, const __half* __restrict__ Al,
    const __half* __restrict__ Bh, const __half* __restrict__ Bl,
    const float* __restrict__ bq, const float* __restrict__ bk,
    const float* __restrict__ bv, const float* __restrict__ resid,
    int mode)
{
    __shared__ __align__(128) __half sA[2][128 * 32];   // 8KB per buffer
    __shared__ __align__(128) __half sB[2][128 * 32];

    const int tid    = threadIdx.x;
    const int lane   = tid & 31;
    const int wid    = tid >> 5;
    const int warp_m = wid & 1;       // 0..1
    const int warp_n = wid >> 1;      // 0..3
    const int n0     = blockIdx.x * 128;
    const int m0     = blockIdx.y * 128;

    const u32 sA_base = smem_u32(sA);
    const u32 sB_base = smem_u32(sB);

    // loader geometry: 2 x 16B units per buffer per matrix
    int lrow[2], lsoff[2], lgcol[2];
    #pragma unroll
    for (int i = 0; i < 2; i++) {
        int u = i * 256 + tid;
        lrow[i]  = u >> 2;
        int c16  = u & 3;
        lsoff[i] = SWZ64(lrow[i] * 64 + c16 * 16);
        lgcol[i] = c16 * 8;
    }

    // ldmatrix addresses: swizzle applied to FULL offset incl. ks (bugfix)
    u32 a_off[4][2], b_off[4][2];
    {
        int arow = warp_m * 64 + (lane & 15);
        int acol = (lane >> 4) * 16;
        #pragma unroll
        for (int mt = 0; mt < 4; mt++)
            #pragma unroll
            for (int ks = 0; ks < 2; ks++)
                a_off[mt][ks] = SWZ64((arow + mt * 16) * 64 + acol + ks * 32);
        int brow = warp_n * 32 + (lane & 7);
        int bcol = ((lane >> 3) & 1) * 16;
        #pragma unroll
        for (int nt = 0; nt < 4; nt++)
            #pragma unroll
            for (int ks = 0; ks < 2; ks++)
                b_off[nt][ks] = SWZ64((brow + nt * 8) * 64 + bcol + ks * 32);
    }

    float acc[4][4][4];
    #pragma unroll
    for (int mt = 0; mt < 4; mt++)
        #pragma unroll
        for (int nt = 0; nt < 4; nt++)
            #pragma unroll
            for (int i = 0; i < 4; i++) acc[mt][nt][i] = 0.f;

    const __half* Ap[3] = { Ah, Ah, Al };
    const __half* Bp[3] = { Bh, Bl, Bh };
    const int NITER = 96;              // 3 passes x 32 chunks

    // prefetch chunk 0
    {
        const __half* A = Ap[0];
        const __half* B = Bp[0];
        #pragma unroll
        for (int i = 0; i < 2; i++) {
            CP_ASYNC16(sA_base + lsoff[i], A + (size_t)(m0 + lrow[i]) * HIDDEN + lgcol[i]);
            CP_ASYNC16(sB_base + lsoff[i], B + (size_t)(n0 + lrow[i]) * HIDDEN + lgcol[i]);
        }
        CP_COMMIT();
    }

    #pragma unroll 1
    for (int it = 0; it < NITER; it++) {
        // prefetch next chunk into other buffer
        if (it + 1 < NITER) {
            int nxt = it + 1;
            const __half* A = Ap[nxt >> 5];
            const __half* B = Bp[nxt >> 5];
            int kb = (nxt & 31) * 32;
            u32 sa = sA_base + ((nxt & 1) ? 8192 : 0);
            u32 sb = sB_base + ((nxt & 1) ? 8192 : 0);
            #pragma unroll
            for (int i = 0; i < 2; i++) {
                CP_ASYNC16(sa + lsoff[i], A + (size_t)(m0 + lrow[i]) * HIDDEN + kb + lgcol[i]);
                CP_ASYNC16(sb + lsoff[i], B + (size_t)(n0 + lrow[i]) * HIDDEN + kb + lgcol[i]);
            }
            CP_COMMIT();
            CP_WAIT(1);
        } else {
            CP_WAIT(0);
        }
        __syncthreads();

        u32 sa = sA_base + ((it & 1) ? 8192 : 0);
        u32 sb = sB_base + ((it & 1) ? 8192 : 0);

        #pragma unroll
        for (int ks = 0; ks < 2; ks++) {
            u32 af[4][4], bf[4][2];
            #pragma unroll
            for (int mt = 0; mt < 4; mt++)
                LDSM_X4(af[mt][0], af[mt][1], af[mt][2], af[mt][3], sa + a_off[mt][ks]);
            #pragma unroll
            for (int nt = 0; nt < 4; nt++)
                LDSM_X2(bf[nt][0], bf[nt][1], sb + b_off[nt][ks]);
            #pragma unroll
            for (int mt = 0; mt < 4; mt++)
                #pragma unroll
                for (int nt = 0; nt < 4; nt++)
                    MMA16816(acc[mt][nt], af[mt], bf[nt]);
        }
        __syncthreads();
    }

    // ---------------- epilogue ----------------
    const int lane4 = lane >> 2;          // row within 8
    const int lane2 = (lane & 3) * 2;     // col pair
    const int z = n0 >> 10;               // matrix id for mode 0
    const float* bias = (mode == 1) ? bq : (z == 0 ? bq : (z == 1 ? bk : bv));
    float* qout = (z == 0) ? g_q : (z == 1 ? g_k : g_v);

    #pragma unroll
    for (int mt = 0; mt < 4; mt++) {
        int r0 = m0 + warp_m * 64 + mt * 16 + lane4;
        #pragma unroll
        for (int nt = 0; nt < 4; nt++) {
            int jj = n0 + warp_n * 32 + nt * 8 + lane2;
            float b0 = bias[(mode == 0) ? (jj & 1023) : jj];
            float b1 = bias[((mode == 0) ? (jj & 1023) : jj) + 1];
            const float* a = acc[mt][nt];
            if (mode == 0) {
                int jm = jj & 1023;
                int h = jm >> 6, d = jm & 63;
                #pragma unroll
                for (int rr = 0; rr < 2; rr++) {
                    int r = r0 + rr * 8;
                    int bb = r >> 11, s = r & (SEQ - 1);
                    float2 v; v.x = a[rr * 2 + 0] + b0; v.y = a[rr * 2 + 1] + b1;
                    *(float2*)&qout[(((size_t)bb * HEADS + h) * SEQ + s) * HEAD_DIM + d] = v;
                }
            } else {
                #pragma unroll
                for (int rr = 0; rr < 2; rr++) {
                    int r = r0 + rr * 8;
                    size_t idx = (size_t)r * HIDDEN + jj;
                    float2 rs = *(const float2*)&resid[idx];
                    float2 v; v.x = a[rr * 2 + 0] + b0 + rs.x; v.y = a[rr * 2 + 1] + b1 + rs.y;
                    *(float2*)&g_res[idx] = v;
                }
            }
        }
    }
}

// =================================================================
// flash attention, fp32 SIMT (unchanged)
// =================================================================
__global__ __launch_bounds__(128) void attn_kernel(const int* __restrict__ mask)
{
    const int bh = blockIdx.y;
    const int b = bh / HEADS;
    const int q0 = blockIdx.x * 32;
    const int tid = threadIdx.x;
    const int lane = tid & 31;
    const int warp = tid >> 5;
    const int r0 = warp * 8;
    const int h = bh % HEADS;

    __shared__ float  Qs[32][68];
    __shared__ float2 Vs[32][32];

    const float4* Qg = (const float4*)(g_q + ((size_t)bh * SEQ + q0) * HEAD_DIM);
    #pragma unroll
    for (int i = 0; i < 4; i++) {
        int idx4 = tid + i * 128;
        int row = idx4 >> 4;
        int c4  = idx4 & 15;
        float4 v = Qg[idx4];
        *(float4*)&Qs[row][c4 * 4] = v;
    }

    float mrow[8], lrow[8], o0[8], o1[8];
    #pragma unroll
    for (int r = 0; r < 8; r++) {
        mrow[r] = -CUDART_INF_F; lrow[r] = 0.f; o0[r] = 0.f; o1[r] = 0.f;
    }

    const float4* Kg = (const float4*)(g_k + (size_t)bh * SEQ * HEAD_DIM);
    const float2* Vg = (const float2*)(g_v + (size_t)bh * SEQ * HEAD_DIM);
    const int* maskb = mask + b * SEQ;

    for (int k0 = 0; k0 < SEQ; k0 += 32) {
        __syncthreads();
        #pragma unroll
        for (int i = 0; i < 8; i++) {
            int idx = tid + i * 128;
            ((float2*)Vs)[idx] = Vg[(size_t)k0 * 32 + idx];
        }
        __syncthreads();

        float4 kr[16];
        #pragma unroll
        for (int i = 0; i < 16; i++) kr[i] = Kg[(size_t)(k0 + lane) * 16 + i];

        float biasv = (1.0f - (float)maskb[k0 + lane]) * -1e18f;

        #pragma unroll
        for (int r = 0; r < 8; r++) {
            const float4* qrow = (const float4*)&Qs[r0 + r][0];
            float s = 0.f;
            #pragma unroll
            for (int i = 0; i < 16; i++) {
                float4 q = qrow[i];
                s += q.x * kr[i].x + q.y * kr[i].y + q.z * kr[i].z + q.w * kr[i].w;
            }
            s = s * ATT_SCALE + biasv;

            float tm = s;
            #pragma unroll
            for (int off = 16; off > 0; off >>= 1)
                tm = fmaxf(tm, __shfl_xor_sync(0xffffffffu, tm, off));
            float mnew = fmaxf(mrow[r], tm);
            float pp = __expf(s - mnew);
            float alpha = __expf(mrow[r] - mnew);
            float ps = pp;
            #pragma unroll
            for (int off = 16; off > 0; off >>= 1)
                ps += __shfl_xor_sync(0xffffffffu, ps, off);
            lrow[r] = lrow[r] * alpha + ps;
            mrow[r] = mnew;
            o0[r] *= alpha; o1[r] *= alpha;

            #pragma unroll
            for (int k = 0; k < 32; k++) {
                float pk = __shfl_sync(0xffffffffu, pp, k);
                float2 v = Vs[k][lane];
                o0[r] += pk * v.x;
                o1[r] += pk * v.y;
            }
        }
    }

    #pragma unroll
    for (int r = 0; r < 8; r++) {
        int tok = b * SEQ + q0 + r0 + r;
        float inv = 1.0f / lrow[r];
        float* dst = g_ctx + (size_t)tok * HIDDEN + h * HEAD_DIM + lane * 2;
        dst[0] = o0[r] * inv;
        dst[1] = o1[r] * inv;
    }
}

// =================================================================
// LayerNorm (unchanged)
// =================================================================
__global__ __launch_bounds__(256) void ln_kernel(
    const float* __restrict__ gamma, const float* __restrict__ beta,
    float* __restrict__ out)
{
    const int rowi = blockIdx.x;
    const int tid = threadIdx.x;
    const int lane = tid & 31;
    const int warp = tid >> 5;

    __shared__ float red[8];
    __shared__ float mean_s, rstd_s;

    const float4* src = (const float4*)(g_res + (size_t)rowi * HIDDEN);
    float4 v = src[tid];

    float sum = v.x + v.y + v.z + v.w;
    #pragma unroll
    for (int off = 16; off > 0; off >>= 1) sum += __shfl_xor_sync(0xffffffffu, sum, off);
    if (lane == 0) red[warp] = sum;
    __syncthreads();
    if (tid == 0) {
        float t = 0.f;
        #pragma unroll
        for (int i = 0; i < 8; i++) t += red[i];
        mean_s = t * (1.0f / HIDDEN);
    }
    __syncthreads();
    float mean = mean_s;

    float dx = v.x - mean, dy = v.y - mean, dz = v.z - mean, dw = v.w - mean;
    float sq = dx * dx + dy * dy + dz * dz + dw * dw;
    #pragma unroll
    for (int off = 16; off > 0; off >>= 1) sq += __shfl_xor_sync(0xffffffffu, sq, off);
    if (lane == 0) red[warp] = sq;
    __syncthreads();
    if (tid == 0) {
        float t = 0.f;
        #pragma unroll
        for (int i = 0; i < 8; i++) t += red[i];
        rstd_s = rsqrtf(t * (1.0f / HIDDEN) + LN_EPS);
    }
    __syncthreads();
    float rstd = rstd_s;

    float4 g = ((const float4*)gamma)[tid];
    float4 bb = ((const float4*)beta)[tid];
    float4 o;
    o.x = dx * rstd * g.x + bb.x;
    o.y = dy * rstd * g.y + bb.y;
    o.z = dz * rstd * g.z + bb.z;
    o.w = dw * rstd * g.w + bb.w;
    ((float4*)(out + (size_t)rowi * HIDDEN))[tid] = o;
}

// =================================================================
extern "C" void kernel_launch(void* const* d_in, const int* in_sizes, int n_in,
                              void* d_out, int out_size)
{
    const float* x    = (const float*)d_in[0];
    const int*   mask = (const int*)  d_in[1];
    const float* Wq   = (const float*)d_in[2];
    const float* bq   = (const float*)d_in[3];
    const float* Wk   = (const float*)d_in[4];
    const float* bk   = (const float*)d_in[5];
    const float* Wv   = (const float*)d_in[6];
    const float* bv   = (const float*)d_in[7];
    const float* Wo   = (const float*)d_in[8];
    const float* bo   = (const float*)d_in[9];
    const float* lng  = (const float*)d_in[10];
    const float* lnb  = (const float*)d_in[11];
    float* out = (float*)d_out;

    __half *xh, *xl, *wh, *wl, *woh, *wol, *ch, *cl;
    cudaGetSymbolAddress((void**)&xh,  g_xh);  cudaGetSymbolAddress((void**)&xl,  g_xl);
    cudaGetSymbolAddress((void**)&wh,  g_wh);  cudaGetSymbolAddress((void**)&wl,  g_wl);
    cudaGetSymbolAddress((void**)&woh, g_woh); cudaGetSymbolAddress((void**)&wol, g_wol);
    cudaGetSymbolAddress((void**)&ch,  g_ch);  cudaGetSymbolAddress((void**)&cl,  g_cl);
    float* ctx;
    cudaGetSymbolAddress((void**)&ctx, g_ctx);

    const int HH4 = HIDDEN * HIDDEN / 4;           // 262144
    const int XN4 = NTOK * HIDDEN / 4;             // 1048576

    // fp16 hi/lo splits
    split_kernel<<<XN4 / 256, 256>>>(x, xh, xl, XN4);
    split_kernel<<<HH4 / 256, 256>>>(Wq, wh,                       wl,                       HH4);
    split_kernel<<<HH4 / 256, 256>>>(Wk, wh + HIDDEN * HIDDEN,     wl + HIDDEN * HIDDEN,     HH4);
    split_kernel<<<HH4 / 256, 256>>>(Wv, wh + 2 * HIDDEN * HIDDEN, wl + 2 * HIDDEN * HIDDEN, HH4);
    split_kernel<<<HH4 / 256, 256>>>(Wo, woh, wol, HH4);

    // QKV projection: C[4096, 3072]
    gemm_hmma_kernel<<<dim3(24, 32), 256>>>(xh, xl, wh, wl, bq, bk, bv, nullptr, 0);

    // attention (SIMT)
    attn_kernel<<<dim3(SEQ / 32, BATCH * HEADS), 128>>>(mask);

    // split ctx, then O-proj + bias + residual
    split_kernel<<<XN4 / 256, 256>>>(ctx, ch, cl, XN4);
    gemm_hmma_kernel<<<dim3(8, 32), 256>>>(ch, cl, woh, wol, bo, nullptr, nullptr, x, 1);

    ln_kernel<<<NTOK, 256>>>(lng, lnb, out);
}

// round 5
// speedup vs baseline: 10.7114x; 8.8253x over previous
#include <cuda_runtime.h>
#include <cuda_fp16.h>
#include <math_constants.h>

#define HIDDEN   1024
#define HEADS    16
#define HEAD_DIM 64
#define BATCH    2
#define SEQ      2048
#define NTOK     (BATCH * SEQ)   // 4096
#define LN_EPS   1e-6f
// 0.125 * log2(e)
#define SCALE_L2E 0.1803368801111f

typedef unsigned int       u32;
typedef unsigned long long u64;

// ---------------- scratch (no allocations allowed) ----------------
__device__ __half g_xh [NTOK * HIDDEN];         // fp16 hidden_states
__device__ __half g_wh [3 * HIDDEN * HIDDEN];   // Wq|Wk|Wv fp16
__device__ __half g_woh[HIDDEN * HIDDEN];       // Wo fp16
__device__ __half g_qh [NTOK * HIDDEN];         // [B,h,S,d] fp16
__device__ __half g_kh [NTOK * HIDDEN];         // [B,h,S,d] fp16
__device__ __half g_vh [NTOK * HIDDEN];         // [B,h,S,d] fp16
__device__ __half g_ctxh[NTOK * HIDDEN];        // [tok, H] fp16
__device__ float  g_res[NTOK * HIDDEN];         // [tok, H] fp32
__device__ float  g_maskt[NTOK];                // (1-mask)*-1e30 per (b,key)

// =================================================================
// helpers
// =================================================================
__device__ __forceinline__ u32 smem_u32(const void* p) {
    u32 a;
    asm("{ .reg .u64 t; cvta.to.shared.u64 t, %1; cvt.u32.u64 %0, t; }" : "=r"(a) : "l"(p));
    return a;
}
#define SWZ64(o)  ((o) ^ (((o) >> 3) & 0x30))   // 64B rows
#define SWZ128(o) ((o) ^ (((o) >> 3) & 0x70))   // 128B rows

#define CP_ASYNC16(dst_u32, src_ptr) \
    asm volatile("cp.async.cg.shared.global [%0], [%1], 16;" :: "r"(dst_u32), "l"(src_ptr) : "memory")
#define CP_COMMIT() asm volatile("cp.async.commit_group;" ::: "memory")
#define CP_WAIT(n)  asm volatile("cp.async.wait_group %0;" :: "n"(n) : "memory")

#define LDSM_X4(r0, r1, r2, r3, addr) \
    asm volatile("ldmatrix.sync.aligned.m8n8.x4.shared.b16 {%0,%1,%2,%3}, [%4];" \
                 : "=r"(r0), "=r"(r1), "=r"(r2), "=r"(r3) : "r"(addr))
#define LDSM_X2(r0, r1, addr) \
    asm volatile("ldmatrix.sync.aligned.m8n8.x2.shared.b16 {%0,%1}, [%2];" \
                 : "=r"(r0), "=r"(r1) : "r"(addr))
#define LDSM_X4_T(r0, r1, r2, r3, addr) \
    asm volatile("ldmatrix.sync.aligned.m8n8.x4.trans.shared.b16 {%0,%1,%2,%3}, [%4];" \
                 : "=r"(r0), "=r"(r1), "=r"(r2), "=r"(r3) : "r"(addr))

#define MMA16816(d, a, b0v, b1v) \
    asm volatile("mma.sync.aligned.m16n8k16.row.col.f32.f16.f16.f32 " \
                 "{%0,%1,%2,%3}, {%4,%5,%6,%7}, {%8,%9}, {%0,%1,%2,%3};" \
                 : "+f"((d)[0]), "+f"((d)[1]), "+f"((d)[2]), "+f"((d)[3]) \
                 : "r"((a)[0]), "r"((a)[1]), "r"((a)[2]), "r"((a)[3]), \
                   "r"(b0v), "r"(b1v))

__device__ __forceinline__ float ex2f(float x) {
    float y;
    asm("ex2.approx.f32 %0, %1;" : "=f"(y) : "f"(x));
    return y;
}
__device__ __forceinline__ u32 packh2(float a, float b) {
    __half2 h = __floats2half2_rn(a, b);
    return *(u32*)&h;
}

// =================================================================
// fp32 -> fp16 convert
// =================================================================
__global__ __launch_bounds__(256) void cvt_kernel(
    const float* __restrict__ src, __half* __restrict__ dst, int n4)
{
    int i = blockIdx.x * blockDim.x + threadIdx.x;
    if (i >= n4) return;
    float4 v = ((const float4*)src)[i];
    ((__half2*)dst)[2 * i]     = __floats2half2_rn(v.x, v.y);
    ((__half2*)dst)[2 * i + 1] = __floats2half2_rn(v.z, v.w);
}

// mask -> additive bias in exp2 domain
__global__ __launch_bounds__(256) void maskt_kernel(const int* __restrict__ mask)
{
    int i = blockIdx.x * blockDim.x + threadIdx.x;
    if (i < NTOK) g_maskt[i] = (1.0f - (float)mask[i]) * -1e30f;
}

// =================================================================
// HMMA GEMM: C[m,n] = sum_k A[m,k]*B[n,k], fp16 in, fp32 accum.
// CTA tile 128x128, BK=32, 8 warps (2m x 4n), double-buffered.
// mode 0: QKV epilogue (+bias, fp16 scatter to g_qh/g_kh/g_vh)
// mode 1: O-proj epilogue (+bias +residual -> g_res fp32)
// =================================================================
__global__ __launch_bounds__(256) void gemm_hmma_kernel(
    const __half* __restrict__ A, const __half* __restrict__ B,
    const float* __restrict__ bq, const float* __restrict__ bk,
    const float* __restrict__ bv, const float* __restrict__ resid,
    int mode)
{
    __shared__ __align__(128) __half sA[2][128 * 32];   // 8KB per buffer
    __shared__ __align__(128) __half sB[2][128 * 32];

    const int tid    = threadIdx.x;
    const int lane   = tid & 31;
    const int wid    = tid >> 5;
    const int warp_m = wid & 1;
    const int warp_n = wid >> 1;
    const int n0     = blockIdx.x * 128;
    const int m0     = blockIdx.y * 128;

    const u32 sA_base = smem_u32(sA);
    const u32 sB_base = smem_u32(sB);

    int lrow[2], lsoff[2], lgcol[2];
    #pragma unroll
    for (int i = 0; i < 2; i++) {
        int u = i * 256 + tid;
        lrow[i]  = u >> 2;
        int c16  = u & 3;
        lsoff[i] = SWZ64(lrow[i] * 64 + c16 * 16);
        lgcol[i] = c16 * 8;
    }

    u32 a_off[4][2], b_off[4][2];
    {
        int arow = warp_m * 64 + (lane & 15);
        int acol = (lane >> 4) * 16;
        #pragma unroll
        for (int mt = 0; mt < 4; mt++)
            #pragma unroll
            for (int ks = 0; ks < 2; ks++)
                a_off[mt][ks] = SWZ64((arow + mt * 16) * 64 + acol + ks * 32);
        int brow = warp_n * 32 + (lane & 7);
        int bcol = ((lane >> 3) & 1) * 16;
        #pragma unroll
        for (int nt = 0; nt < 4; nt++)
            #pragma unroll
            for (int ks = 0; ks < 2; ks++)
                b_off[nt][ks] = SWZ64((brow + nt * 8) * 64 + bcol + ks * 32);
    }

    float acc[4][4][4];
    #pragma unroll
    for (int mt = 0; mt < 4; mt++)
        #pragma unroll
        for (int nt = 0; nt < 4; nt++)
            #pragma unroll
            for (int i = 0; i < 4; i++) acc[mt][nt][i] = 0.f;

    const int NITER = 32;

    #pragma unroll
    for (int i = 0; i < 2; i++) {
        CP_ASYNC16(sA_base + lsoff[i], A + (size_t)(m0 + lrow[i]) * HIDDEN + lgcol[i]);
        CP_ASYNC16(sB_base + lsoff[i], B + (size_t)(n0 + lrow[i]) * HIDDEN + lgcol[i]);
    }
    CP_COMMIT();

    #pragma unroll 1
    for (int it = 0; it < NITER; it++) {
        if (it + 1 < NITER) {
            int kb = (it + 1) * 32;
            u32 sa = sA_base + ((it + 1) & 1) * 8192;
            u32 sb = sB_base + ((it + 1) & 1) * 8192;
            #pragma unroll
            for (int i = 0; i < 2; i++) {
                CP_ASYNC16(sa + lsoff[i], A + (size_t)(m0 + lrow[i]) * HIDDEN + kb + lgcol[i]);
                CP_ASYNC16(sb + lsoff[i], B + (size_t)(n0 + lrow[i]) * HIDDEN + kb + lgcol[i]);
            }
            CP_COMMIT();
            CP_WAIT(1);
        } else {
            CP_WAIT(0);
        }
        __syncthreads();

        u32 sa = sA_base + (it & 1) * 8192;
        u32 sb = sB_base + (it & 1) * 8192;

        #pragma unroll
        for (int ks = 0; ks < 2; ks++) {
            u32 af[4][4], bf[4][2];
            #pragma unroll
            for (int mt = 0; mt < 4; mt++)
                LDSM_X4(af[mt][0], af[mt][1], af[mt][2], af[mt][3], sa + a_off[mt][ks]);
            #pragma unroll
            for (int nt = 0; nt < 4; nt++)
                LDSM_X2(bf[nt][0], bf[nt][1], sb + b_off[nt][ks]);
            #pragma unroll
            for (int mt = 0; mt < 4; mt++)
                #pragma unroll
                for (int nt = 0; nt < 4; nt++)
                    MMA16816(acc[mt][nt], af[mt], bf[nt][0], bf[nt][1]);
        }
        __syncthreads();
    }

    // ---------------- epilogue ----------------
    const int lane4 = lane >> 2;
    const int lane2 = (lane & 3) * 2;
    const int z = n0 >> 10;
    const float* bias = (mode == 1) ? bq : (z == 0 ? bq : (z == 1 ? bk : bv));
    __half* qout = (z == 0) ? g_qh : (z == 1 ? g_kh : g_vh);

    #pragma unroll
    for (int mt = 0; mt < 4; mt++) {
        int r0 = m0 + warp_m * 64 + mt * 16 + lane4;
        #pragma unroll
        for (int nt = 0; nt < 4; nt++) {
            int jj = n0 + warp_n * 32 + nt * 8 + lane2;
            const float* a = acc[mt][nt];
            if (mode == 0) {
                int jm = jj & 1023;
                float b0 = bias[jm], b1 = bias[jm + 1];
                int h = jm >> 6, d = jm & 63;
                #pragma unroll
                for (int rr = 0; rr < 2; rr++) {
                    int r = r0 + rr * 8;
                    int bb = r >> 11, s = r & (SEQ - 1);
                    __half2 hv = __floats2half2_rn(a[rr * 2 + 0] + b0, a[rr * 2 + 1] + b1);
                    *(__half2*)&qout[(((size_t)bb * HEADS + h) * SEQ + s) * HEAD_DIM + d] = hv;
                }
            } else {
                float b0 = bias[jj], b1 = bias[jj + 1];
                #pragma unroll
                for (int rr = 0; rr < 2; rr++) {
                    int r = r0 + rr * 8;
                    size_t idx = (size_t)r * HIDDEN + jj;
                    float2 rs = *(const float2*)&resid[idx];
                    float2 v; v.x = a[rr * 2 + 0] + b0 + rs.x; v.y = a[rr * 2 + 1] + b1 + rs.y;
                    *(float2*)&g_res[idx] = v;
                }
            }
        }
    }
}

// =================================================================
// HMMA flash attention. grid (SEQ/128, B*HEADS), 256 threads (8 warps).
// Each warp: 16 query rows. BN=64 keys/tile, d=64.
// Q frags in regs, K via ldmatrix, V via ldmatrix.trans, P in regs.
// Online softmax in exp2 domain. Output fp16 ctx [tok, H].
// =================================================================
__global__ __launch_bounds__(256) void attn_hmma_kernel()
{
    __shared__ __align__(128) unsigned char sm[32768];  // [2 stages][K 8KB | V 8KB]

    const int tid  = threadIdx.x;
    const int lane = tid & 31;
    const int warp = tid >> 5;
    const int bh   = blockIdx.y;
    const int b    = bh >> 4;
    const int h    = bh & 15;
    const int q0   = blockIdx.x * 128;

    const __half* Qg = g_qh + (size_t)bh * SEQ * HEAD_DIM;
    const __half* Kg = g_kh + (size_t)bh * SEQ * HEAD_DIM;
    const __half* Vg = g_vh + (size_t)bh * SEQ * HEAD_DIM;
    const float* mtb = g_maskt + b * SEQ;

    const u32 base = smem_u32(sm);

    // ---- stage Q [128 x 64] fp16 into smem, then ldmatrix to regs ----
    #pragma unroll
    for (int i = 0; i < 4; i++) {
        int u = i * 256 + tid;
        int row = u >> 3, c16 = u & 7;
        CP_ASYNC16(base + SWZ128(row * 128 + c16 * 16),
                   Qg + (size_t)(q0 + row) * HEAD_DIM + c16 * 8);
    }
    CP_COMMIT();
    CP_WAIT(0);
    __syncthreads();

    u32 qf[4][4];
    {
        int qrow = warp * 16 + (lane & 15);
        #pragma unroll
        for (int kk = 0; kk < 4; kk++) {
            u32 off = SWZ128(qrow * 128 + kk * 32 + (lane >> 4) * 16);
            LDSM_X4(qf[kk][0], qf[kk][1], qf[kk][2], qf[kk][3], base + off);
        }
    }
    __syncthreads();

    // precomputed ldmatrix offsets
    u32 kso[4], vo[4];
    {
        int krow = lane & 7;
        int kcol = ((lane >> 3) & 1) * 16;
        #pragma unroll
        for (int ks = 0; ks < 4; ks++)
            kso[ks] = SWZ128(krow * 128 + kcol + ks * 32);
        int vrow = (lane & 7) + ((lane >> 3) & 1) * 8;
        int vcol = (lane >> 4) * 16;
        #pragma unroll
        for (int np = 0; np < 4; np++)
            vo[np] = SWZ128(vrow * 128 + np * 32 + vcol);
    }

    float o[8][4];
    #pragma unroll
    for (int nt = 0; nt < 8; nt++)
        #pragma unroll
        for (int e = 0; e < 4; e++) o[nt][e] = 0.f;
    float mt0 = -CUDART_INF_F, mt1 = -CUDART_INF_F;
    float l0 = 0.f, l1 = 0.f;

    // prologue: prefetch ktile 0 into stage 0
    #define LOADKV(kt_, st_) do {                                                   \
        u32 db_ = base + (st_) * 16384;                                             \
        const __half* Ks_ = Kg + (size_t)(kt_) * 64 * HEAD_DIM;                     \
        const __half* Vs_ = Vg + (size_t)(kt_) * 64 * HEAD_DIM;                     \
        _Pragma("unroll")                                                           \
        for (int i_ = 0; i_ < 2; i_++) {                                            \
            int u_ = i_ * 256 + tid;                                                \
            int r_ = u_ >> 3, c_ = u_ & 7;                                          \
            u32 o_ = SWZ128(r_ * 128 + c_ * 16);                                    \
            CP_ASYNC16(db_ + o_,        Ks_ + (size_t)r_ * HEAD_DIM + c_ * 8);      \
            CP_ASYNC16(db_ + 8192 + o_, Vs_ + (size_t)r_ * HEAD_DIM + c_ * 8);      \
        }                                                                           \
    } while (0)

    LOADKV(0, 0);
    CP_COMMIT();

    const int NKT = SEQ / 64;   // 32
    #pragma unroll 1
    for (int kt = 0; kt < NKT; kt++) {
        if (kt + 1 < NKT) {
            LOADKV(kt + 1, (kt + 1) & 1);
            CP_COMMIT();
            CP_WAIT(1);
        } else {
            CP_WAIT(0);
        }
        __syncthreads();

        u32 kb = base + (kt & 1) * 16384;
        u32 vb = kb + 8192;

        // ---- S = Q @ K^T ----
        float sf[8][4];
        #pragma unroll
        for (int nt = 0; nt < 8; nt++) {
            #pragma unroll
            for (int e = 0; e < 4; e++) sf[nt][e] = 0.f;
            #pragma unroll
            for (int ks = 0; ks < 4; ks++) {
                u32 k0, k1;
                LDSM_X2(k0, k1, kb + nt * 1024 + kso[ks]);
                MMA16816(sf[nt], qf[ks], k0, k1);
            }
        }

        // ---- scale + bias into exp2 domain; row maxes ----
        float rm0 = -CUDART_INF_F, rm1 = -CUDART_INF_F;
        #pragma unroll
        for (int nt = 0; nt < 8; nt++) {
            float2 bb = *(const float2*)&mtb[kt * 64 + nt * 8 + (lane & 3) * 2];
            sf[nt][0] = sf[nt][0] * SCALE_L2E + bb.x;
            sf[nt][1] = sf[nt][1] * SCALE_L2E + bb.y;
            sf[nt][2] = sf[nt][2] * SCALE_L2E + bb.x;
            sf[nt][3] = sf[nt][3] * SCALE_L2E + bb.y;
            rm0 = fmaxf(rm0, fmaxf(sf[nt][0], sf[nt][1]));
            rm1 = fmaxf(rm1, fmaxf(sf[nt][2], sf[nt][3]));
        }
        rm0 = fmaxf(rm0, __shfl_xor_sync(0xffffffffu, rm0, 1));
        rm0 = fmaxf(rm0, __shfl_xor_sync(0xffffffffu, rm0, 2));
        rm1 = fmaxf(rm1, __shfl_xor_sync(0xffffffffu, rm1, 1));
        rm1 = fmaxf(rm1, __shfl_xor_sync(0xffffffffu, rm1, 2));

        float mn0 = fmaxf(mt0, rm0), mn1 = fmaxf(mt1, rm1);
        float a0 = ex2f(mt0 - mn0), a1 = ex2f(mt1 - mn1);
        mt0 = mn0; mt1 = mn1;
        l0 *= a0; l1 *= a1;
        #pragma unroll
        for (int nt = 0; nt < 8; nt++) {
            o[nt][0] *= a0; o[nt][1] *= a0;
            o[nt][2] *= a1; o[nt][3] *= a1;
        }

        // ---- exponentiate; partial row sums ----
        #pragma unroll
        for (int nt = 0; nt < 8; nt++) {
            sf[nt][0] = ex2f(sf[nt][0] - mn0);
            sf[nt][1] = ex2f(sf[nt][1] - mn0);
            sf[nt][2] = ex2f(sf[nt][2] - mn1);
            sf[nt][3] = ex2f(sf[nt][3] - mn1);
            l0 += sf[nt][0] + sf[nt][1];
            l1 += sf[nt][2] + sf[nt][3];
        }

        // ---- O += P @ V ----
        #pragma unroll
        for (int kk = 0; kk < 4; kk++) {
            u32 pf[4];
            pf[0] = packh2(sf[2 * kk][0],     sf[2 * kk][1]);
            pf[1] = packh2(sf[2 * kk][2],     sf[2 * kk][3]);
            pf[2] = packh2(sf[2 * kk + 1][0], sf[2 * kk + 1][1]);
            pf[3] = packh2(sf[2 * kk + 1][2], sf[2 * kk + 1][3]);
            #pragma unroll
            for (int np = 0; np < 4; np++) {
                u32 v0, v1, v2, v3;
                LDSM_X4_T(v0, v1, v2, v3, vb + kk * 2048 + vo[np]);
                MMA16816(o[2 * np],     pf, v0, v1);
                MMA16816(o[2 * np + 1], pf, v2, v3);
            }
        }
        __syncthreads();
    }

    // ---- finalize: combine l across quad, normalize, write fp16 ctx ----
    l0 += __shfl_xor_sync(0xffffffffu, l0, 1);
    l0 += __shfl_xor_sync(0xffffffffu, l0, 2);
    l1 += __shfl_xor_sync(0xffffffffu, l1, 1);
    l1 += __shfl_xor_sync(0xffffffffu, l1, 2);
    float inv0 = 1.0f / l0, inv1 = 1.0f / l1;

    int srow0 = q0 + warp * 16 + (lane >> 2);
    size_t tok0 = (size_t)(b * SEQ + srow0) * HIDDEN;
    size_t tok1 = tok0 + 8 * HIDDEN;
    int colb = h * HEAD_DIM + (lane & 3) * 2;
    #pragma unroll
    for (int nt = 0; nt < 8; nt++) {
        int col = colb + nt * 8;
        *(__half2*)&g_ctxh[tok0 + col] = __floats2half2_rn(o[nt][0] * inv0, o[nt][1] * inv0);
        *(__half2*)&g_ctxh[tok1 + col] = __floats2half2_rn(o[nt][2] * inv1, o[nt][3] * inv1);
    }
}

// =================================================================
// LayerNorm over last dim (1024). One block per token row.
// =================================================================
__global__ __launch_bounds__(256) void ln_kernel(
    const float* __restrict__ gamma, const float* __restrict__ beta,
    float* __restrict__ out)
{
    const int rowi = blockIdx.x;
    const int tid = threadIdx.x;
    const int lane = tid & 31;
    const int warp = tid >> 5;

    __shared__ float red[8];
    __shared__ float mean_s, rstd_s;

    const float4* src = (const float4*)(g_res + (size_t)rowi * HIDDEN);
    float4 v = src[tid];

    float sum = v.x + v.y + v.z + v.w;
    #pragma unroll
    for (int off = 16; off > 0; off >>= 1) sum += __shfl_xor_sync(0xffffffffu, sum, off);
    if (lane == 0) red[warp] = sum;
    __syncthreads();
    if (tid == 0) {
        float t = 0.f;
        #pragma unroll
        for (int i = 0; i < 8; i++) t += red[i];
        mean_s = t * (1.0f / HIDDEN);
    }
    __syncthreads();
    float mean = mean_s;

    float dx = v.x - mean, dy = v.y - mean, dz = v.z - mean, dw = v.w - mean;
    float sq = dx * dx + dy * dy + dz * dz + dw * dw;
    #pragma unroll
    for (int off = 16; off > 0; off >>= 1) sq += __shfl_xor_sync(0xffffffffu, sq, off);
    if (lane == 0) red[warp] = sq;
    __syncthreads();
    if (tid == 0) {
        float t = 0.f;
        #pragma unroll
        for (int i = 0; i < 8; i++) t += red[i];
        rstd_s = rsqrtf(t * (1.0f / HIDDEN) + LN_EPS);
    }
    __syncthreads();
    float rstd = rstd_s;

    float4 g = ((const float4*)gamma)[tid];
    float4 bb = ((const float4*)beta)[tid];
    float4 o;
    o.x = dx * rstd * g.x + bb.x;
    o.y = dy * rstd * g.y + bb.y;
    o.z = dz * rstd * g.z + bb.z;
    o.w = dw * rstd * g.w + bb.w;
    ((float4*)(out + (size_t)rowi * HIDDEN))[tid] = o;
}

// =================================================================
extern "C" void kernel_launch(void* const* d_in, const int* in_sizes, int n_in,
                              void* d_out, int out_size)
{
    const float* x    = (const float*)d_in[0];
    const int*   mask = (const int*)  d_in[1];
    const float* Wq   = (const float*)d_in[2];
    const float* bq   = (const float*)d_in[3];
    const float* Wk   = (const float*)d_in[4];
    const float* bk   = (const float*)d_in[5];
    const float* Wv   = (const float*)d_in[6];
    const float* bv   = (const float*)d_in[7];
    const float* Wo   = (const float*)d_in[8];
    const float* bo   = (const float*)d_in[9];
    const float* lng  = (const float*)d_in[10];
    const float* lnb  = (const float*)d_in[11];
    float* out = (float*)d_out;

    __half *xh, *wh, *woh, *ctxh;
    cudaGetSymbolAddress((void**)&xh,   g_xh);
    cudaGetSymbolAddress((void**)&wh,   g_wh);
    cudaGetSymbolAddress((void**)&woh,  g_woh);
    cudaGetSymbolAddress((void**)&ctxh, g_ctxh);

    const int HH4 = HIDDEN * HIDDEN / 4;   // 262144
    const int XN4 = NTOK * HIDDEN / 4;     // 1048576

    // fp16 conversions
    cvt_kernel<<<XN4 / 256, 256>>>(x, xh, XN4);
    cvt_kernel<<<HH4 / 256, 256>>>(Wq, wh,                       HH4);
    cvt_kernel<<<HH4 / 256, 256>>>(Wk, wh + HIDDEN * HIDDEN,     HH4);
    cvt_kernel<<<HH4 / 256, 256>>>(Wv, wh + 2 * HIDDEN * HIDDEN, HH4);
    cvt_kernel<<<HH4 / 256, 256>>>(Wo, woh, HH4);
    maskt_kernel<<<NTOK / 256, 256>>>(mask);

    // QKV projection -> fp16 q/k/v in [B,h,S,d]
    gemm_hmma_kernel<<<dim3(24, 32), 256>>>(xh, wh, bq, bk, bv, nullptr, 0);

    // flash attention (HMMA) -> fp16 ctx
    attn_hmma_kernel<<<dim3(SEQ / 128, BATCH * HEADS), 256>>>();

    // O-proj + bias + residual -> fp32 res
    gemm_hmma_kernel<<<dim3(8, 32), 256>>>(ctxh, woh, bo, nullptr, nullptr, x, 1);

    ln_kernel<<<NTOK, 256>>>(lng, lnb, out);
}

// round 6
// speedup vs baseline: 12.5577x; 1.1724x over previous
#include <cuda_runtime.h>
#include <cuda_fp16.h>
#include <math_constants.h>

#define HIDDEN   1024
#define HEADS    16
#define HEAD_DIM 64
#define BATCH    2
#define SEQ      2048
#define NTOK     (BATCH * SEQ)   // 4096
#define LN_EPS   1e-6f
// 0.125 * log2(e)
#define SCALE_L2E 0.1803368801111f

typedef unsigned int       u32;
typedef unsigned long long u64;

// ---------------- scratch (no allocations allowed) ----------------
__device__ __half g_xh [NTOK * HIDDEN];         // fp16 hidden_states
__device__ __half g_wh [3 * HIDDEN * HIDDEN];   // Wq|Wk|Wv fp16
__device__ __half g_woh[HIDDEN * HIDDEN];       // Wo fp16
__device__ __half g_qh [NTOK * HIDDEN];         // [B,h,S,d] fp16
__device__ __half g_kh [NTOK * HIDDEN];         // [B,h,S,d] fp16
__device__ __half g_vh [NTOK * HIDDEN];         // [B,h,S,d] fp16
__device__ __half g_ctxh[NTOK * HIDDEN];        // [tok, H] fp16
__device__ float  g_res[NTOK * HIDDEN];         // [tok, H] fp32
__device__ float  g_maskt[NTOK];                // (1-mask)*-1e30 per (b,key)

// =================================================================
// helpers
// =================================================================
__device__ __forceinline__ u32 smem_u32(const void* p) {
    u32 a;
    asm("{ .reg .u64 t; cvta.to.shared.u64 t, %1; cvt.u32.u64 %0, t; }" : "=r"(a) : "l"(p));
    return a;
}
#define SWZ64(o)  ((o) ^ (((o) >> 3) & 0x30))   // 64B rows
#define SWZ128(o) ((o) ^ (((o) >> 3) & 0x70))   // 128B rows

#define CP_ASYNC16(dst_u32, src_ptr) \
    asm volatile("cp.async.cg.shared.global [%0], [%1], 16;" :: "r"(dst_u32), "l"(src_ptr) : "memory")
#define CP_COMMIT() asm volatile("cp.async.commit_group;" ::: "memory")
#define CP_WAIT0()  asm volatile("cp.async.wait_group 0;" ::: "memory")
#define CP_WAIT1()  asm volatile("cp.async.wait_group 1;" ::: "memory")
#define CP_WAIT2()  asm volatile("cp.async.wait_group 2;" ::: "memory")

#define LDSM_X4(r0, r1, r2, r3, addr) \
    asm volatile("ldmatrix.sync.aligned.m8n8.x4.shared.b16 {%0,%1,%2,%3}, [%4];" \
                 : "=r"(r0), "=r"(r1), "=r"(r2), "=r"(r3) : "r"(addr))
#define LDSM_X2(r0, r1, addr) \
    asm volatile("ldmatrix.sync.aligned.m8n8.x2.shared.b16 {%0,%1}, [%2];" \
                 : "=r"(r0), "=r"(r1) : "r"(addr))
#define LDSM_X4_T(r0, r1, r2, r3, addr) \
    asm volatile("ldmatrix.sync.aligned.m8n8.x4.trans.shared.b16 {%0,%1,%2,%3}, [%4];" \
                 : "=r"(r0), "=r"(r1), "=r"(r2), "=r"(r3) : "r"(addr))

#define MMA16816(d, a, b0v, b1v) \
    asm volatile("mma.sync.aligned.m16n8k16.row.col.f32.f16.f16.f32 " \
                 "{%0,%1,%2,%3}, {%4,%5,%6,%7}, {%8,%9}, {%0,%1,%2,%3};" \
                 : "+f"((d)[0]), "+f"((d)[1]), "+f"((d)[2]), "+f"((d)[3]) \
                 : "r"((a)[0]), "r"((a)[1]), "r"((a)[2]), "r"((a)[3]), \
                   "r"(b0v), "r"(b1v))

__device__ __forceinline__ float ex2f(float x) {
    float y;
    asm("ex2.approx.f32 %0, %1;" : "=f"(y) : "f"(x));
    return y;
}
__device__ __forceinline__ u32 packh2(float a, float b) {
    __half2 h = __floats2half2_rn(a, b);
    return *(u32*)&h;
}

// =================================================================
// converts
// =================================================================
__global__ __launch_bounds__(256) void cvt_kernel(
    const float* __restrict__ src, __half* __restrict__ dst, int n4)
{
    int i = blockIdx.x * blockDim.x + threadIdx.x;
    if (i >= n4) return;
    float4 v = ((const float4*)src)[i];
    ((__half2*)dst)[2 * i]     = __floats2half2_rn(v.x, v.y);
    ((__half2*)dst)[2 * i + 1] = __floats2half2_rn(v.z, v.w);
}

// 4 weight matrices in one launch: z=0..2 -> g_wh segments, z=3 -> g_woh
__global__ __launch_bounds__(256) void wcvt_kernel(
    const float* __restrict__ Wq, const float* __restrict__ Wk,
    const float* __restrict__ Wv, const float* __restrict__ Wo)
{
    int z = blockIdx.y;
    const float* src = (z == 0) ? Wq : (z == 1) ? Wk : (z == 2) ? Wv : Wo;
    __half* dst = (z == 3) ? g_woh : (g_wh + (size_t)z * HIDDEN * HIDDEN);
    int i = blockIdx.x * blockDim.x + threadIdx.x;
    float4 v = ((const float4*)src)[i];
    ((__half2*)dst)[2 * i]     = __floats2half2_rn(v.x, v.y);
    ((__half2*)dst)[2 * i + 1] = __floats2half2_rn(v.z, v.w);
}

__global__ __launch_bounds__(256) void maskt_kernel(const int* __restrict__ mask)
{
    int i = blockIdx.x * blockDim.x + threadIdx.x;
    if (i < NTOK) g_maskt[i] = (1.0f - (float)mask[i]) * -1e30f;
}

// =================================================================
// HMMA GEMM: C[m,n] = sum_k A[m,k]*B[n,k], fp16 in, fp32 accum.
// CTA tile 128x128, BK=32, 8 warps (2m x 4n).
// 4-stage cp.async ring, prefetch distance 2, ONE barrier/iter.
// Dynamic smem: 4 stages x (A 8KB | B 8KB) = 64KB.
// mode 0: QKV epilogue (+bias, fp16 scatter to g_qh/g_kh/g_vh)
// mode 1: O-proj epilogue (+bias +residual -> g_res fp32)
// =================================================================
__global__ __launch_bounds__(256, 2) void gemm_hmma_kernel(
    const __half* __restrict__ A, const __half* __restrict__ B,
    const float* __restrict__ bq, const float* __restrict__ bk,
    const float* __restrict__ bv, const float* __restrict__ resid,
    int mode)
{
    extern __shared__ __align__(128) unsigned char dsm[];

    const int tid    = threadIdx.x;
    const int lane   = tid & 31;
    const int wid    = tid >> 5;
    const int warp_m = wid & 1;
    const int warp_n = wid >> 1;
    const int n0     = blockIdx.x * 128;
    const int m0     = blockIdx.y * 128;

    const u32 base = smem_u32(dsm);

    int lrow[2], lsoff[2], lgcol[2];
    #pragma unroll
    for (int i = 0; i < 2; i++) {
        int u = i * 256 + tid;
        lrow[i]  = u >> 2;
        int c16  = u & 3;
        lsoff[i] = SWZ64(lrow[i] * 64 + c16 * 16);
        lgcol[i] = c16 * 8;
    }

    u32 a_off[4][2], b_off[4][2];
    {
        int arow = warp_m * 64 + (lane & 15);
        int acol = (lane >> 4) * 16;
        #pragma unroll
        for (int mt = 0; mt < 4; mt++)
            #pragma unroll
            for (int ks = 0; ks < 2; ks++)
                a_off[mt][ks] = SWZ64((arow + mt * 16) * 64 + acol + ks * 32);
        int brow = warp_n * 32 + (lane & 7);
        int bcol = ((lane >> 3) & 1) * 16;
        #pragma unroll
        for (int nt = 0; nt < 4; nt++)
            #pragma unroll
            for (int ks = 0; ks < 2; ks++)
                b_off[nt][ks] = SWZ64((brow + nt * 8) * 64 + bcol + ks * 32);
    }

    float acc[4][4][4];
    #pragma unroll
    for (int mt = 0; mt < 4; mt++)
        #pragma unroll
        for (int nt = 0; nt < 4; nt++)
            #pragma unroll
            for (int i = 0; i < 4; i++) acc[mt][nt][i] = 0.f;

    const int NITER = 32;

    #define G_LOAD(it_) do {                                                        \
        u32 sa_ = base + ((it_) & 3) * 16384;                                       \
        u32 sb_ = sa_ + 8192;                                                       \
        int kb_ = (it_) * 32;                                                       \
        _Pragma("unroll")                                                           \
        for (int i_ = 0; i_ < 2; i_++) {                                            \
            CP_ASYNC16(sa_ + lsoff[i_], A + (size_t)(m0 + lrow[i_]) * HIDDEN + kb_ + lgcol[i_]); \
            CP_ASYNC16(sb_ + lsoff[i_], B + (size_t)(n0 + lrow[i_]) * HIDDEN + kb_ + lgcol[i_]); \
        }                                                                           \
        CP_COMMIT();                                                                \
    } while (0)

    G_LOAD(0);
    G_LOAD(1);

    #pragma unroll 1
    for (int it = 0; it < NITER; it++) {
        if (it + 2 < NITER) { G_LOAD(it + 2); CP_WAIT2(); }
        else if (it + 1 < NITER) { CP_WAIT1(); }
        else { CP_WAIT0(); }
        __syncthreads();

        u32 sa = base + (it & 3) * 16384;
        u32 sb = sa + 8192;

        #pragma unroll
        for (int ks = 0; ks < 2; ks++) {
            u32 af[4][4], bf[4][2];
            #pragma unroll
            for (int mt = 0; mt < 4; mt++)
                LDSM_X4(af[mt][0], af[mt][1], af[mt][2], af[mt][3], sa + a_off[mt][ks]);
            #pragma unroll
            for (int nt = 0; nt < 4; nt++)
                LDSM_X2(bf[nt][0], bf[nt][1], sb + b_off[nt][ks]);
            #pragma unroll
            for (int mt = 0; mt < 4; mt++)
                #pragma unroll
                for (int nt = 0; nt < 4; nt++)
                    MMA16816(acc[mt][nt], af[mt], bf[nt][0], bf[nt][1]);
        }
    }

    // ---------------- epilogue (regs only, no barrier needed) ----------------
    const int lane4 = lane >> 2;
    const int lane2 = (lane & 3) * 2;
    const int z = n0 >> 10;
    const float* bias = (mode == 1) ? bq : (z == 0 ? bq : (z == 1 ? bk : bv));
    __half* qout = (z == 0) ? g_qh : (z == 1 ? g_kh : g_vh);

    #pragma unroll
    for (int mt = 0; mt < 4; mt++) {
        int r0 = m0 + warp_m * 64 + mt * 16 + lane4;
        #pragma unroll
        for (int nt = 0; nt < 4; nt++) {
            int jj = n0 + warp_n * 32 + nt * 8 + lane2;
            const float* a = acc[mt][nt];
            if (mode == 0) {
                int jm = jj & 1023;
                float b0 = bias[jm], b1 = bias[jm + 1];
                int h = jm >> 6, d = jm & 63;
                #pragma unroll
                for (int rr = 0; rr < 2; rr++) {
                    int r = r0 + rr * 8;
                    int bb = r >> 11, s = r & (SEQ - 1);
                    __half2 hv = __floats2half2_rn(a[rr * 2 + 0] + b0, a[rr * 2 + 1] + b1);
                    *(__half2*)&qout[(((size_t)bb * HEADS + h) * SEQ + s) * HEAD_DIM + d] = hv;
                }
            } else {
                float b0 = bias[jj], b1 = bias[jj + 1];
                #pragma unroll
                for (int rr = 0; rr < 2; rr++) {
                    int r = r0 + rr * 8;
                    size_t idx = (size_t)r * HIDDEN + jj;
                    float2 rs = *(const float2*)&resid[idx];
                    float2 v; v.x = a[rr * 2 + 0] + b0 + rs.x; v.y = a[rr * 2 + 1] + b1 + rs.y;
                    *(float2*)&g_res[idx] = v;
                }
            }
        }
    }
    #undef G_LOAD
}

// =================================================================
// HMMA flash attention. grid (SEQ/128, B*HEADS), 256 threads (8 warps).
// Each warp: 16 query rows. BN=64 keys/tile, d=64.
// 4-stage cp.async ring (K 8KB | V 8KB per stage = 64KB dynamic smem),
// prefetch distance 2, ONE barrier/iter.
// =================================================================
__global__ __launch_bounds__(256, 2) void attn_hmma_kernel()
{
    extern __shared__ __align__(128) unsigned char dsm[];

    const int tid  = threadIdx.x;
    const int lane = tid & 31;
    const int warp = tid >> 5;
    const int bh   = blockIdx.y;
    const int b    = bh >> 4;
    const int h    = bh & 15;
    const int q0   = blockIdx.x * 128;

    const __half* Qg = g_qh + (size_t)bh * SEQ * HEAD_DIM;
    const __half* Kg = g_kh + (size_t)bh * SEQ * HEAD_DIM;
    const __half* Vg = g_vh + (size_t)bh * SEQ * HEAD_DIM;
    const float* mtb = g_maskt + b * SEQ;

    const u32 base = smem_u32(dsm);

    // ---- stage Q [128 x 64] into stage-0 region (16KB), then to regs ----
    #pragma unroll
    for (int i = 0; i < 4; i++) {
        int u = i * 256 + tid;
        int row = u >> 3, c16 = u & 7;
        CP_ASYNC16(base + SWZ128(row * 128 + c16 * 16),
                   Qg + (size_t)(q0 + row) * HEAD_DIM + c16 * 8);
    }
    CP_COMMIT();
    CP_WAIT0();
    __syncthreads();

    u32 qf[4][4];
    {
        int qrow = warp * 16 + (lane & 15);
        #pragma unroll
        for (int kk = 0; kk < 4; kk++) {
            u32 off = SWZ128(qrow * 128 + kk * 32 + (lane >> 4) * 16);
            LDSM_X4(qf[kk][0], qf[kk][1], qf[kk][2], qf[kk][3], base + off);
        }
    }
    __syncthreads();    // all warps done reading Q before stage 0 is overwritten

    u32 kso[4], vo[4];
    {
        int krow = lane & 7;
        int kcol = ((lane >> 3) & 1) * 16;
        #pragma unroll
        for (int ks = 0; ks < 4; ks++)
            kso[ks] = SWZ128(krow * 128 + kcol + ks * 32);
        int vrow = (lane & 7) + ((lane >> 3) & 1) * 8;
        int vcol = (lane >> 4) * 16;
        #pragma unroll
        for (int np = 0; np < 4; np++)
            vo[np] = SWZ128(vrow * 128 + np * 32 + vcol);
    }

    float o[8][4];
    #pragma unroll
    for (int nt = 0; nt < 8; nt++)
        #pragma unroll
        for (int e = 0; e < 4; e++) o[nt][e] = 0.f;
    float mt0 = -CUDART_INF_F, mt1 = -CUDART_INF_F;
    float l0 = 0.f, l1 = 0.f;

    #define LOADKV(kt_) do {                                                        \
        u32 db_ = base + ((kt_) & 3) * 16384;                                       \
        const __half* Ks_ = Kg + (size_t)(kt_) * 64 * HEAD_DIM;                     \
        const __half* Vs_ = Vg + (size_t)(kt_) * 64 * HEAD_DIM;                     \
        _Pragma("unroll")                                                           \
        for (int i_ = 0; i_ < 2; i_++) {                                            \
            int u_ = i_ * 256 + tid;                                                \
            int r_ = u_ >> 3, c_ = u_ & 7;                                          \
            u32 o_ = SWZ128(r_ * 128 + c_ * 16);                                    \
            CP_ASYNC16(db_ + o_,        Ks_ + (size_t)r_ * HEAD_DIM + c_ * 8);      \
            CP_ASYNC16(db_ + 8192 + o_, Vs_ + (size_t)r_ * HEAD_DIM + c_ * 8);      \
        }                                                                           \
        CP_COMMIT();                                                                \
    } while (0)

    LOADKV(0);
    LOADKV(1);

    const int NKT = SEQ / 64;   // 32
    #pragma unroll 1
    for (int kt = 0; kt < NKT; kt++) {
        if (kt + 2 < NKT) { LOADKV(kt + 2); CP_WAIT2(); }
        else if (kt + 1 < NKT) { CP_WAIT1(); }
        else { CP_WAIT0(); }
        __syncthreads();

        u32 kb = base + (kt & 3) * 16384;
        u32 vb = kb + 8192;

        // ---- S = Q @ K^T ----
        float sf[8][4];
        #pragma unroll
        for (int nt = 0; nt < 8; nt++) {
            #pragma unroll
            for (int e = 0; e < 4; e++) sf[nt][e] = 0.f;
            #pragma unroll
            for (int ks = 0; ks < 4; ks++) {
                u32 k0, k1;
                LDSM_X2(k0, k1, kb + nt * 1024 + kso[ks]);
                MMA16816(sf[nt], qf[ks], k0, k1);
            }
        }

        // ---- scale + mask bias (exp2 domain); row maxes ----
        float rm0 = -CUDART_INF_F, rm1 = -CUDART_INF_F;
        #pragma unroll
        for (int nt = 0; nt < 8; nt++) {
            float2 bb = *(const float2*)&mtb[kt * 64 + nt * 8 + (lane & 3) * 2];
            sf[nt][0] = sf[nt][0] * SCALE_L2E + bb.x;
            sf[nt][1] = sf[nt][1] * SCALE_L2E + bb.y;
            sf[nt][2] = sf[nt][2] * SCALE_L2E + bb.x;
            sf[nt][3] = sf[nt][3] * SCALE_L2E + bb.y;
            rm0 = fmaxf(rm0, fmaxf(sf[nt][0], sf[nt][1]));
            rm1 = fmaxf(rm1, fmaxf(sf[nt][2], sf[nt][3]));
        }
        rm0 = fmaxf(rm0, __shfl_xor_sync(0xffffffffu, rm0, 1));
        rm0 = fmaxf(rm0, __shfl_xor_sync(0xffffffffu, rm0, 2));
        rm1 = fmaxf(rm1, __shfl_xor_sync(0xffffffffu, rm1, 1));
        rm1 = fmaxf(rm1, __shfl_xor_sync(0xffffffffu, rm1, 2));

        float mn0 = fmaxf(mt0, rm0), mn1 = fmaxf(mt1, rm1);
        float a0 = ex2f(mt0 - mn0), a1 = ex2f(mt1 - mn1);
        mt0 = mn0; mt1 = mn1;
        l0 *= a0; l1 *= a1;
        #pragma unroll
        for (int nt = 0; nt < 8; nt++) {
            o[nt][0] *= a0; o[nt][1] *= a0;
            o[nt][2] *= a1; o[nt][3] *= a1;
        }

        // ---- exponentiate; partial row sums ----
        #pragma unroll
        for (int nt = 0; nt < 8; nt++) {
            sf[nt][0] = ex2f(sf[nt][0] - mn0);
            sf[nt][1] = ex2f(sf[nt][1] - mn0);
            sf[nt][2] = ex2f(sf[nt][2] - mn1);
            sf[nt][3] = ex2f(sf[nt][3] - mn1);
            l0 += sf[nt][0] + sf[nt][1];
            l1 += sf[nt][2] + sf[nt][3];
        }

        // ---- O += P @ V ----
        #pragma unroll
        for (int kk = 0; kk < 4; kk++) {
            u32 pf[4];
            pf[0] = packh2(sf[2 * kk][0],     sf[2 * kk][1]);
            pf[1] = packh2(sf[2 * kk][2],     sf[2 * kk][3]);
            pf[2] = packh2(sf[2 * kk + 1][0], sf[2 * kk + 1][1]);
            pf[3] = packh2(sf[2 * kk + 1][2], sf[2 * kk + 1][3]);
            #pragma unroll
            for (int np = 0; np < 4; np++) {
                u32 v0, v1, v2, v3;
                LDSM_X4_T(v0, v1, v2, v3, vb + kk * 2048 + vo[np]);
                MMA16816(o[2 * np],     pf, v0, v1);
                MMA16816(o[2 * np + 1], pf, v2, v3);
            }
        }
    }

    // ---- finalize ----
    l0 += __shfl_xor_sync(0xffffffffu, l0, 1);
    l0 += __shfl_xor_sync(0xffffffffu, l0, 2);
    l1 += __shfl_xor_sync(0xffffffffu, l1, 1);
    l1 += __shfl_xor_sync(0xffffffffu, l1, 2);
    float inv0 = 1.0f / l0, inv1 = 1.0f / l1;

    int srow0 = q0 + warp * 16 + (lane >> 2);
    size_t tok0 = (size_t)(b * SEQ + srow0) * HIDDEN;
    size_t tok1 = tok0 + 8 * HIDDEN;
    int colb = h * HEAD_DIM + (lane & 3) * 2;
    #pragma unroll
    for (int nt = 0; nt < 8; nt++) {
        int col = colb + nt * 8;
        *(__half2*)&g_ctxh[tok0 + col] = __floats2half2_rn(o[nt][0] * inv0, o[nt][1] * inv0);
        *(__half2*)&g_ctxh[tok1 + col] = __floats2half2_rn(o[nt][2] * inv1, o[nt][3] * inv1);
    }
    #undef LOADKV
}

// =================================================================
// LayerNorm over last dim (1024). One block per token row.
// =================================================================
__global__ __launch_bounds__(256) void ln_kernel(
    const float* __restrict__ gamma, const float* __restrict__ beta,
    float* __restrict__ out)
{
    const int rowi = blockIdx.x;
    const int tid = threadIdx.x;
    const int lane = tid & 31;
    const int warp = tid >> 5;

    __shared__ float red[8];
    __shared__ float mean_s, rstd_s;

    const float4* src = (const float4*)(g_res + (size_t)rowi * HIDDEN);
    float4 v = src[tid];

    float sum = v.x + v.y + v.z + v.w;
    #pragma unroll
    for (int off = 16; off > 0; off >>= 1) sum += __shfl_xor_sync(0xffffffffu, sum, off);
    if (lane == 0) red[warp] = sum;
    __syncthreads();
    if (tid == 0) {
        float t = 0.f;
        #pragma unroll
        for (int i = 0; i < 8; i++) t += red[i];
        mean_s = t * (1.0f / HIDDEN);
    }
    __syncthreads();
    float mean = mean_s;

    float dx = v.x - mean, dy = v.y - mean, dz = v.z - mean, dw = v.w - mean;
    float sq = dx * dx + dy * dy + dz * dz + dw * dw;
    #pragma unroll
    for (int off = 16; off > 0; off >>= 1) sq += __shfl_xor_sync(0xffffffffu, sq, off);
    if (lane == 0) red[warp] = sq;
    __syncthreads();
    if (tid == 0) {
        float t = 0.f;
        #pragma unroll
        for (int i = 0; i < 8; i++) t += red[i];
        rstd_s = rsqrtf(t * (1.0f / HIDDEN) + LN_EPS);
    }
    __syncthreads();
    float rstd = rstd_s;

    float4 g = ((const float4*)gamma)[tid];
    float4 bb = ((const float4*)beta)[tid];
    float4 o;
    o.x = dx * rstd * g.x + bb.x;
    o.y = dy * rstd * g.y + bb.y;
    o.z = dz * rstd * g.z + bb.z;
    o.w = dw * rstd * g.w + bb.w;
    ((float4*)(out + (size_t)rowi * HIDDEN))[tid] = o;
}

// =================================================================
extern "C" void kernel_launch(void* const* d_in, const int* in_sizes, int n_in,
                              void* d_out, int out_size)
{
    const float* x    = (const float*)d_in[0];
    const int*   mask = (const int*)  d_in[1];
    const float* Wq   = (const float*)d_in[2];
    const float* bq   = (const float*)d_in[3];
    const float* Wk   = (const float*)d_in[4];
    const float* bk   = (const float*)d_in[5];
    const float* Wv   = (const float*)d_in[6];
    const float* bv   = (const float*)d_in[7];
    const float* Wo   = (const float*)d_in[8];
    const float* bo   = (const float*)d_in[9];
    const float* lng  = (const float*)d_in[10];
    const float* lnb  = (const float*)d_in[11];
    float* out = (float*)d_out;

    __half *xh, *wh, *woh, *ctxh;
    cudaGetSymbolAddress((void**)&xh,   g_xh);
    cudaGetSymbolAddress((void**)&wh,   g_wh);
    cudaGetSymbolAddress((void**)&woh,  g_woh);
    cudaGetSymbolAddress((void**)&ctxh, g_ctxh);

    static bool attr_set = false;
    if (!attr_set) {
        cudaFuncSetAttribute(gemm_hmma_kernel, cudaFuncAttributeMaxDynamicSharedMemorySize, 65536);
        cudaFuncSetAttribute(attn_hmma_kernel, cudaFuncAttributeMaxDynamicSharedMemorySize, 65536);
        attr_set = true;
    }

    const int HH4 = HIDDEN * HIDDEN / 4;   // 262144
    const int XN4 = NTOK * HIDDEN / 4;     // 1048576

    cvt_kernel<<<XN4 / 256, 256>>>(x, xh, XN4);
    wcvt_kernel<<<dim3(HH4 / 256, 4), 256>>>(Wq, Wk, Wv, Wo);
    maskt_kernel<<<NTOK / 256, 256>>>(mask);

    // QKV projection -> fp16 q/k/v in [B,h,S,d]
    gemm_hmma_kernel<<<dim3(24, 32), 256, 65536>>>(xh, wh, bq, bk, bv, nullptr, 0);

    // flash attention (HMMA) -> fp16 ctx
    attn_hmma_kernel<<<dim3(SEQ / 128, BATCH * HEADS), 256, 65536>>>();

    // O-proj + bias + residual -> fp32 res
    gemm_hmma_kernel<<<dim3(8, 32), 256, 65536>>>(ctxh, woh, bo, nullptr, nullptr, x, 1);

    ln_kernel<<<NTOK, 256>>>(lng, lnb, out);
}